// round 12
// baseline (speedup 1.0000x reference)
#include <cuda_runtime.h>
#include <cuda_fp16.h>
#include <cstdint>

#define B_DIM 1024
#define K_DIM 512
#define H_DIM 512
#define J_DIM 256
#define D_DIM 4

#define SCALE_F 512.0f
#define INV_SCALE (1.0f/512.0f)

__device__ __forceinline__ uint32_t smem_u32(const void* p) {
    uint32_t a;
    asm("{ .reg .u64 t; cvta.to.shared.u64 t, %1; cvt.u32.u64 %0, t; }" : "=r"(a) : "l"(p));
    return a;
}

#define LDSM_X4(r0,r1,r2,r3,addr) \
    asm volatile("ldmatrix.sync.aligned.m8n8.x4.shared.b16 {%0,%1,%2,%3}, [%4];" \
        : "=r"(r0), "=r"(r1), "=r"(r2), "=r"(r3) : "r"(addr))

#define MMA16816(d, a, b0, b1) \
    asm volatile("mma.sync.aligned.m16n8k16.row.col.f32.f16.f16.f32 " \
        "{%0,%1,%2,%3}, {%4,%5,%6,%7}, {%8,%9}, {%0,%1,%2,%3};" \
        : "+f"((d)[0]), "+f"((d)[1]), "+f"((d)[2]), "+f"((d)[3]) \
        : "r"((a)[0]), "r"((a)[1]), "r"((a)[2]), "r"((a)[3]), "r"(b0), "r"(b1))

// ---------------- single fused kernel ----------------
// CTA = (j, m_tile of 128).
//   X tile: xeff = x * wi[j] * 512 -> fp16, built once (128KB, swizzled).
//   W0: streamed fp32 -> regs -> fp16 smem per 128h x 64k stage (16KB x 2 buf).
//       LDGs issued after kk=0 MMAs, converted+stored after kk=3 (latency
//       covered by ~3 MMA blocks).
// 8 warps 2M x 4N, warp tile 64m x 32h. 32 stages; epilogue every 8th into mu.
__global__ void __launch_bounds__(256, 1)
encoder_fused(const float* __restrict__ x, const int* __restrict__ ip,
              const float* __restrict__ w, const float* __restrict__ W0,
              const float* __restrict__ b0g, const float* __restrict__ W1g,
              const float* __restrict__ b1g, const float* __restrict__ logvar,
              float* __restrict__ out, int out_size) {
    extern __shared__ char smem[];
    const uint32_t sbase = smem_u32(smem);
    const uint32_t S_X = sbase;              // 131072 B
    const uint32_t S_H = sbase + 131072;     // 2 x 16384 B (fp16 W stage)
    float2* bw   = reinterpret_cast<float2*>(smem + 163840);  // 512 float2
    float*  sums = reinterpret_cast<float*>(smem + 167936);   // 128 floats
    float*  wis  = reinterpret_cast<float*>(smem + 168448);   // 512 floats

    const int tid  = threadIdx.x;
    const int wid  = tid >> 5;
    const int lane = tid & 31;
    const int wm = wid & 1;          // M block (64 rows)
    const int wn = wid >> 1;         // [0,4): 32-h block
    const int j   = blockIdx.x >> 3;
    const int mt8 = blockIdx.x & 7;

    // wi (pre-scaled), b0/W1, sums, logvar tail
    const float* wsrc = w + (size_t)ip[0] * J_DIM * K_DIM + (size_t)j * K_DIM;
    for (int c = tid; c < K_DIM; c += 256) wis[c] = wsrc[c] * SCALE_F;
    for (int c = tid; c < H_DIM; c += 256)
        bw[c] = make_float2(b0g[j * H_DIM + c], W1g[j * H_DIM + c]);
    if (tid < 128) sums[tid] = 0.f;
    if (blockIdx.x == 0) {
        int extra = out_size - B_DIM * J_DIM;
        if (tid < extra && tid < D_DIM) out[B_DIM * J_DIM + tid] = logvar[tid];
    }
    __syncthreads();   // wis visible

    // X tile: xeff = x * wi * 512 -> fp16, swizzled (proven in R10)
    const float* Xb = x + (size_t)(mt8 * 128) * K_DIM;
#pragma unroll 4
    for (int it = 0; it < 32; ++it) {
        int c = tid + it * 256;
        int row = c >> 6, kb = c & 63;
        const float4* xs = reinterpret_cast<const float4*>(Xb + (size_t)row * K_DIM + kb * 8);
        float4 x0 = xs[0], x1 = xs[1];
        const float4* wv = reinterpret_cast<const float4*>(wis + kb * 8);
        float4 w0v = wv[0], w1v = wv[1];
        __half2 h0 = __floats2half2_rn(x0.x * w0v.x, x0.y * w0v.y);
        __half2 h1 = __floats2half2_rn(x0.z * w0v.z, x0.w * w0v.w);
        __half2 h2 = __floats2half2_rn(x1.x * w1v.x, x1.y * w1v.y);
        __half2 h3 = __floats2half2_rn(x1.z * w1v.z, x1.w * w1v.w);
        uint4 pk;
        pk.x = *reinterpret_cast<uint32_t*>(&h0);
        pk.y = *reinterpret_cast<uint32_t*>(&h1);
        pk.z = *reinterpret_cast<uint32_t*>(&h2);
        pk.w = *reinterpret_cast<uint32_t*>(&h3);
        int swz = (kb & 56) | ((kb ^ row) & 7);
        *reinterpret_cast<uint4*>(smem + row * 1024 + swz * 16) = pk;
    }

    const float* W0j = W0 + (size_t)j * H_DIM * K_DIM;

    // stage source: stage s covers h rows [(s>>3)*128, +128), k [(s&7)*64, +64)
    auto stage_src = [&](int s) {
        return W0j + (size_t)((s >> 3) * 128) * K_DIM + (s & 7) * 64;
    };
    // prologue: stage 0 -> H[0] (sync LDG, once)
    {
        const float* src = stage_src(0);
#pragma unroll
        for (int it = 0; it < 8; ++it) {
            int c = tid + it * 256;
            int row = c >> 4, seg = c & 15;
            float4 v0 = *reinterpret_cast<const float4*>(src + (size_t)row * K_DIM + seg * 4);
            __half2 u0 = __floats2half2_rn(v0.x, v0.y);
            __half2 u1 = __floats2half2_rn(v0.z, v0.w);
            uint2 st;
            st.x = *reinterpret_cast<uint32_t*>(&u0);
            st.y = *reinterpret_cast<uint32_t*>(&u1);
            int kb = seg >> 1, hf = seg & 1;
            *reinterpret_cast<uint2*>(smem + 131072 + row * 128 +
                                      ((kb ^ (row & 7)) * 16) + hf * 8) = st;
        }
    }

    float acc[4][4][4];
#pragma unroll
    for (int mt = 0; mt < 4; ++mt)
#pragma unroll
        for (int nt = 0; nt < 4; ++nt)
#pragma unroll
            for (int q = 0; q < 4; ++q) acc[mt][nt][q] = 0.f;

    float mu[4][2];
#pragma unroll
    for (int mt = 0; mt < 4; ++mt) { mu[mt][0] = 0.f; mu[mt][1] = 0.f; }

    const int a_row = wm * 64 + (lane & 15);
    const int a_ck  = lane >> 4;
    const int b_row = wn * 32 + (lane & 7) + ((lane >> 4) << 3);
    const int b_kb  = (lane >> 3) & 1;
    const int h_off = wn * 32 + (lane & 3) * 2;

    uint32_t afr[4][4], bfr[2][4];
    float4 v[8];   // in-flight fp32 W stage (32 regs)

#pragma unroll 1
    for (int cc = 0; cc < 32; ++cc) {
        __syncthreads();   // H[cc&1] stores visible; prev reads of H[(cc+1)&1] done

        uint32_t hb = S_H + (cc & 1) * 16384;
        uint32_t hb2 = S_H + ((cc + 1) & 1) * 16384;
        int ks = cc & 7;
        const bool pf = (cc < 31);
        const float* nsrc = stage_src(cc + 1);   // valid only when pf

#pragma unroll
        for (int kk = 0; kk < 4; ++kk) {
#pragma unroll
            for (int mt = 0; mt < 4; ++mt) {
                int r = a_row + mt * 16;
                int cidx = ks * 8 + kk * 2 + a_ck;
                int swz = (cidx & 56) | ((cidx ^ r) & 7);
                LDSM_X4(afr[mt][0], afr[mt][1], afr[mt][2], afr[mt][3],
                        S_X + r * 1024 + swz * 16);
            }
#pragma unroll
            for (int np = 0; np < 2; ++np) {
                int hl = b_row + np * 16;
                int kb = kk * 2 + b_kb;
                LDSM_X4(bfr[np][0], bfr[np][1], bfr[np][2], bfr[np][3],
                        hb + hl * 128 + ((kb ^ (hl & 7)) * 16));
            }
#pragma unroll
            for (int mt = 0; mt < 4; ++mt)
#pragma unroll
                for (int nt = 0; nt < 4; ++nt)
                    MMA16816(acc[mt][nt], afr[mt],
                             bfr[nt >> 1][(nt & 1) * 2],
                             bfr[nt >> 1][(nt & 1) * 2 + 1]);
            if (kk == 0 && pf) {
                // issue next stage's global loads; consumed after kk=3
#pragma unroll
                for (int it = 0; it < 8; ++it) {
                    int c = tid + it * 256;
                    int row = c >> 4, seg = c & 15;
                    v[it] = *reinterpret_cast<const float4*>(
                        nsrc + (size_t)row * K_DIM + seg * 4);
                }
            }
        }

        if (pf) {
            // convert + store next stage (latency covered by kk=1..3 MMAs)
#pragma unroll
            for (int it = 0; it < 8; ++it) {
                int c = tid + it * 256;
                int row = c >> 4, seg = c & 15;
                __half2 u0 = __floats2half2_rn(v[it].x, v[it].y);
                __half2 u1 = __floats2half2_rn(v[it].z, v[it].w);
                uint2 st;
                st.x = *reinterpret_cast<uint32_t*>(&u0);
                st.y = *reinterpret_cast<uint32_t*>(&u1);
                int kb = seg >> 1, hf = seg & 1;
                *reinterpret_cast<uint2*>(smem + (hb2 - sbase) + row * 128 +
                                          ((kb ^ (row & 7)) * 16) + hf * 8) = st;
            }
        }

        if (ks == 7) {
            // fold finished 128-wide h-chunk (hc = cc>>3) into mu, zero acc
            int hbase = (cc >> 3) * 128;
#pragma unroll
            for (int mt = 0; mt < 4; ++mt) {
                float sA = mu[mt][0], sB = mu[mt][1];
#pragma unroll
                for (int nt = 0; nt < 4; ++nt) {
                    int h = hbase + h_off + nt * 8;
                    float2 bw0 = bw[h];
                    float2 bw1 = bw[h + 1];
                    float vv;
                    vv = fmaf(acc[mt][nt][0], INV_SCALE, bw0.x);
                    vv = (vv > 0.f) ? vv : 0.01f * vv;  sA = fmaf(vv, bw0.y, sA);
                    vv = fmaf(acc[mt][nt][1], INV_SCALE, bw1.x);
                    vv = (vv > 0.f) ? vv : 0.01f * vv;  sA = fmaf(vv, bw1.y, sA);
                    vv = fmaf(acc[mt][nt][2], INV_SCALE, bw0.x);
                    vv = (vv > 0.f) ? vv : 0.01f * vv;  sB = fmaf(vv, bw0.y, sB);
                    vv = fmaf(acc[mt][nt][3], INV_SCALE, bw1.x);
                    vv = (vv > 0.f) ? vv : 0.01f * vv;  sB = fmaf(vv, bw1.y, sB);
#pragma unroll
                    for (int q = 0; q < 4; ++q) acc[mt][nt][q] = 0.f;
                }
                mu[mt][0] = sA; mu[mt][1] = sB;
            }
        }
    }

    // final reduction: shuffle over h-lanes, atomic over warps
#pragma unroll
    for (int mt = 0; mt < 4; ++mt) {
        float sA = mu[mt][0], sB = mu[mt][1];
        sA += __shfl_xor_sync(0xffffffffu, sA, 1);
        sA += __shfl_xor_sync(0xffffffffu, sA, 2);
        sB += __shfl_xor_sync(0xffffffffu, sB, 1);
        sB += __shfl_xor_sync(0xffffffffu, sB, 2);
        if ((lane & 3) == 0) {
            int row = wm * 64 + mt * 16 + (lane >> 2);
            atomicAdd(&sums[row], sA);
            atomicAdd(&sums[row + 8], sB);
        }
    }

    __syncthreads();
    if (tid < 128)
        out[(size_t)(mt8 * 128 + tid) * J_DIM + j] = sums[tid] + b1g[j];
}

// ---------------- launch ----------------
extern "C" void kernel_launch(void* const* d_in, const int* in_sizes, int n_in,
                              void* d_out, int out_size) {
    const float* x      = (const float*)d_in[0];
    const int*   ip     = (const int*)d_in[1];
    const float* w      = (const float*)d_in[2];
    const float* W0     = (const float*)d_in[3];
    const float* b0     = (const float*)d_in[4];
    const float* W1     = (const float*)d_in[5];
    const float* b1     = (const float*)d_in[6];
    const float* logvar = (const float*)d_in[7];
    float* out = (float*)d_out;

    const int SMEM_BYTES = 170496;
    cudaFuncSetAttribute(encoder_fused, cudaFuncAttributeMaxDynamicSharedMemorySize, SMEM_BYTES);

    encoder_fused<<<J_DIM * (B_DIM / 128), 256, SMEM_BYTES>>>(
        x, ip, w, W0, b0, W1, b1, logvar, out, out_size);
}

// round 13
// speedup vs baseline: 1.2539x; 1.2539x over previous
#include <cuda_runtime.h>
#include <cuda_fp16.h>
#include <cstdint>

#define B_DIM 1024
#define K_DIM 512
#define H_DIM 512
#define J_DIM 256
#define D_DIM 4

#define SCALE_F 512.0f
#define INV_SCALE (1.0f/512.0f)

// scratch (static device globals: allocation-free)
__device__ __half g_xh[B_DIM * K_DIM];
__device__ __half g_w0h[(size_t)J_DIM * H_DIM * K_DIM];

__device__ __forceinline__ uint32_t smem_u32(const void* p) {
    uint32_t a;
    asm("{ .reg .u64 t; cvta.to.shared.u64 t, %1; cvt.u32.u64 %0, t; }" : "=r"(a) : "l"(p));
    return a;
}

#define CP_ASYNC16(dst, src) \
    asm volatile("cp.async.cg.shared.global [%0], [%1], 16;" \
        :: "r"((uint32_t)(dst)), "l"(src) : "memory")
#define CP_COMMIT() asm volatile("cp.async.commit_group;" ::: "memory")
#define CP_WAIT(n)  asm volatile("cp.async.wait_group %0;" :: "n"(n) : "memory")

#define LDSM_X4(r0,r1,r2,r3,addr) \
    asm volatile("ldmatrix.sync.aligned.m8n8.x4.shared.b16 {%0,%1,%2,%3}, [%4];" \
        : "=r"(r0), "=r"(r1), "=r"(r2), "=r"(r3) : "r"(addr))

#define MMA16816(d, a, b0, b1) \
    asm volatile("mma.sync.aligned.m16n8k16.row.col.f32.f16.f16.f32 " \
        "{%0,%1,%2,%3}, {%4,%5,%6,%7}, {%8,%9}, {%0,%1,%2,%3};" \
        : "+f"((d)[0]), "+f"((d)[1]), "+f"((d)[2]), "+f"((d)[3]) \
        : "r"((a)[0]), "r"((a)[1]), "r"((a)[2]), "r"((a)[3]), "r"(b0), "r"(b1))

// ---------------- merged prep kernel (known-good) ----------------
__global__ void prep_kernel(const float* __restrict__ W0, const float* __restrict__ w,
                            const int* __restrict__ ip,
                            const float* __restrict__ x, const float* __restrict__ logvar,
                            float* __restrict__ out, int out_size) {
    size_t t = (size_t)blockIdx.x * blockDim.x + threadIdx.x;
    size_t e = t * 4;
    int j = (int)(e >> 18);          // H*K = 2^18
    int k = (int)(e & (K_DIM - 1));
    float4 a = *reinterpret_cast<const float4*>(W0 + e);
    const float* wip = w + (size_t)ip[0] * J_DIM * K_DIM + (size_t)j * K_DIM + k;
    float4 b = *reinterpret_cast<const float4*>(wip);
    __half2 h0 = __floats2half2_rn(a.x * b.x * SCALE_F, a.y * b.y * SCALE_F);
    __half2 h1 = __floats2half2_rn(a.z * b.z * SCALE_F, a.w * b.w * SCALE_F);
    uint2 pk;
    pk.x = *reinterpret_cast<uint32_t*>(&h0);
    pk.y = *reinterpret_cast<uint32_t*>(&h1);
    *reinterpret_cast<uint2*>(g_w0h + e) = pk;

    if (t < (B_DIM * K_DIM) / 4) {
        float4 v = reinterpret_cast<const float4*>(x)[t];
        __half2 x0 = __floats2half2_rn(v.x, v.y);
        __half2 x1 = __floats2half2_rn(v.z, v.w);
        uint2 xp;
        xp.x = *reinterpret_cast<uint32_t*>(&x0);
        xp.y = *reinterpret_cast<uint32_t*>(&x1);
        reinterpret_cast<uint2*>(g_xh)[t] = xp;
    }
    if (blockIdx.x == 0) {
        int extra = out_size - B_DIM * J_DIM;
        if ((int)threadIdx.x < extra && threadIdx.x < D_DIM)
            out[B_DIM * J_DIM + threadIdx.x] = logvar[threadIdx.x];
    }
}

// ---------------- fused grouped-GEMM, 3-stage distance-2 pipeline ----------------
// CTA = (j, m_tile of 128). X tile [128 x 512] fp16 resident (128KB).
// W0eff[j]: 32 stages of 128h x 64k (16KB, RING OF 3, prefetch distance 2).
// 8 warps 2M x 4N, warp tile 64m x 32h. Epilogue folds into mu regs every 8th.
__global__ void __launch_bounds__(256, 1)
encoder_gemm(const float* __restrict__ b0g, const float* __restrict__ W1g,
             const float* __restrict__ b1g, float* __restrict__ out) {
    extern __shared__ char smem[];
    const uint32_t S_X = smem_u32(smem);            // 131072 B
    const uint32_t S_W = S_X + 131072;              // 3 x 16384 B
    float2* bw   = reinterpret_cast<float2*>(smem + 180224);  // 512 float2
    float*  sums = reinterpret_cast<float*>(smem + 184320);   // 128 floats

    const int tid  = threadIdx.x;
    const int wid  = tid >> 5;
    const int lane = tid & 31;
    const int wm = wid & 1;          // M block (64 rows)
    const int wn = wid >> 1;         // [0,4): 32-h block
    const int j  = blockIdx.x >> 3;
    const int mt8 = blockIdx.x & 7;

    const __half* Ab = g_xh + (size_t)(mt8 * 128) * K_DIM;
    const __half* Bb = g_w0h + (size_t)j * H_DIM * K_DIM;

    for (int c = tid; c < H_DIM; c += 256)
        bw[c] = make_float2(b0g[j * H_DIM + c], W1g[j * H_DIM + c]);
    if (tid < 128) sums[tid] = 0.f;

    // X tile: 8192 16B chunks, xor-swizzled (64 chunks per 1024B row)
#pragma unroll
    for (int it = 0; it < 32; ++it) {
        int c = tid + it * 256;
        int row = c >> 6, kb = c & 63;
        int swz = (kb & 56) | ((kb ^ row) & 7);
        CP_ASYNC16(S_X + row * 1024 + swz * 16, Ab + (size_t)row * K_DIM + kb * 8);
    }

    // W stage: cc in [0,32): hc = cc>>3, ks = cc&7. 128h x 64k = 128B/row.
    auto stage_w = [&](int cc, int buf) {
        const __half* src = Bb + (size_t)((cc >> 3) * 128) * K_DIM + (cc & 7) * 64;
        uint32_t dstb = S_W + buf * 16384;
#pragma unroll
        for (int it = 0; it < 4; ++it) {
            int c = tid + it * 256;
            int row = c >> 3, kb = c & 7;
            CP_ASYNC16(dstb + row * 128 + (kb ^ (row & 7)) * 16,
                       src + (size_t)row * K_DIM + kb * 8);
        }
    };

    stage_w(0, 0);
    CP_COMMIT();           // group: X tile + stage 0
    stage_w(1, 1);
    CP_COMMIT();           // group: stage 1

    float acc[4][4][4];
#pragma unroll
    for (int mt = 0; mt < 4; ++mt)
#pragma unroll
        for (int nt = 0; nt < 4; ++nt)
#pragma unroll
            for (int q = 0; q < 4; ++q) acc[mt][nt][q] = 0.f;

    float mu[4][2];
#pragma unroll
    for (int mt = 0; mt < 4; ++mt) { mu[mt][0] = 0.f; mu[mt][1] = 0.f; }

    const int a_row = wm * 64 + (lane & 15);
    const int a_ck  = lane >> 4;
    const int b_row = wn * 32 + (lane & 7) + ((lane >> 4) << 3);
    const int b_kb  = (lane >> 3) & 1;
    const int h_off = wn * 32 + (lane & 3) * 2;

    uint32_t afr[4][4], bfr[2][4];

    int buf = 0;           // buffer of stage cc (cc % 3, tracked incrementally)
#pragma unroll 1
    for (int cc = 0; cc < 32; ++cc) {
        // distance-2 prefetch: stage cc was issued 2 iterations ago
        if (cc < 31) { CP_WAIT(1); } else { CP_WAIT(0); }
        __syncthreads();   // stage cc visible to all; prev reads of buf+2 done

        int nbuf = buf + 2; if (nbuf >= 3) nbuf -= 3;   // (cc+2) % 3
        if (cc < 30) { stage_w(cc + 2, nbuf); CP_COMMIT(); }

        uint32_t wbase = S_W + buf * 16384;
        int ks = cc & 7;

#pragma unroll
        for (int kk = 0; kk < 4; ++kk) {
#pragma unroll
            for (int mt = 0; mt < 4; ++mt) {
                int r = a_row + mt * 16;
                int cidx = ks * 8 + kk * 2 + a_ck;
                int swz = (cidx & 56) | ((cidx ^ r) & 7);
                LDSM_X4(afr[mt][0], afr[mt][1], afr[mt][2], afr[mt][3],
                        S_X + r * 1024 + swz * 16);
            }
#pragma unroll
            for (int np = 0; np < 2; ++np) {
                int hl = b_row + np * 16;
                int kb = kk * 2 + b_kb;
                LDSM_X4(bfr[np][0], bfr[np][1], bfr[np][2], bfr[np][3],
                        wbase + hl * 128 + (kb ^ (hl & 7)) * 16);
            }
#pragma unroll
            for (int mt = 0; mt < 4; ++mt)
#pragma unroll
                for (int nt = 0; nt < 4; ++nt)
                    MMA16816(acc[mt][nt], afr[mt],
                             bfr[nt >> 1][(nt & 1) * 2],
                             bfr[nt >> 1][(nt & 1) * 2 + 1]);
        }

        if (ks == 7) {
            // fold finished 128-wide h-chunk (hc = cc>>3) into mu, zero acc
            int hbase = (cc >> 3) * 128;
#pragma unroll
            for (int mt = 0; mt < 4; ++mt) {
                float sA = mu[mt][0], sB = mu[mt][1];
#pragma unroll
                for (int nt = 0; nt < 4; ++nt) {
                    int h = hbase + h_off + nt * 8;
                    float2 bw0 = bw[h];
                    float2 bw1 = bw[h + 1];
                    float v;
                    v = fmaf(acc[mt][nt][0], INV_SCALE, bw0.x);
                    v = (v > 0.f) ? v : 0.01f * v;  sA = fmaf(v, bw0.y, sA);
                    v = fmaf(acc[mt][nt][1], INV_SCALE, bw1.x);
                    v = (v > 0.f) ? v : 0.01f * v;  sA = fmaf(v, bw1.y, sA);
                    v = fmaf(acc[mt][nt][2], INV_SCALE, bw0.x);
                    v = (v > 0.f) ? v : 0.01f * v;  sB = fmaf(v, bw0.y, sB);
                    v = fmaf(acc[mt][nt][3], INV_SCALE, bw1.x);
                    v = (v > 0.f) ? v : 0.01f * v;  sB = fmaf(v, bw1.y, sB);
#pragma unroll
                    for (int q = 0; q < 4; ++q) acc[mt][nt][q] = 0.f;
                }
                mu[mt][0] = sA; mu[mt][1] = sB;
            }
        }

        if (++buf == 3) buf = 0;
    }

    // final reduction: shuffle over h-lanes, atomic over warps
#pragma unroll
    for (int mt = 0; mt < 4; ++mt) {
        float sA = mu[mt][0], sB = mu[mt][1];
        sA += __shfl_xor_sync(0xffffffffu, sA, 1);
        sA += __shfl_xor_sync(0xffffffffu, sA, 2);
        sB += __shfl_xor_sync(0xffffffffu, sB, 1);
        sB += __shfl_xor_sync(0xffffffffu, sB, 2);
        if ((lane & 3) == 0) {
            int row = wm * 64 + mt * 16 + (lane >> 2);
            atomicAdd(&sums[row], sA);
            atomicAdd(&sums[row + 8], sB);
        }
    }

    __syncthreads();
    if (tid < 128)
        out[(size_t)(mt8 * 128 + tid) * J_DIM + j] = sums[tid] + b1g[j];
}

// ---------------- launch ----------------
extern "C" void kernel_launch(void* const* d_in, const int* in_sizes, int n_in,
                              void* d_out, int out_size) {
    const float* x      = (const float*)d_in[0];
    const int*   ip     = (const int*)d_in[1];
    const float* w      = (const float*)d_in[2];
    const float* W0     = (const float*)d_in[3];
    const float* b0     = (const float*)d_in[4];
    const float* W1     = (const float*)d_in[5];
    const float* b1     = (const float*)d_in[6];
    const float* logvar = (const float*)d_in[7];
    float* out = (float*)d_out;

    const int SMEM_BYTES = 184832;
    cudaFuncSetAttribute(encoder_gemm, cudaFuncAttributeMaxDynamicSharedMemorySize, SMEM_BYTES);

    prep_kernel<<<(J_DIM * H_DIM * K_DIM / 4) / 256, 256>>>(W0, w, ip, x, logvar, out, out_size);
    encoder_gemm<<<J_DIM * (B_DIM / 128), 256, SMEM_BYTES>>>(b0, W1, b1, out);
}

// round 14
// speedup vs baseline: 1.3683x; 1.0913x over previous
#include <cuda_runtime.h>
#include <cuda_fp16.h>
#include <cstdint>

#define B_DIM 1024
#define K_DIM 512
#define H_DIM 512
#define J_DIM 256
#define D_DIM 4

#define SCALE_F 512.0f
#define INV_SCALE (1.0f/512.0f)

// scratch (static device globals: allocation-free)
__device__ __half g_xh[B_DIM * K_DIM];
__device__ __half g_w0h[(size_t)J_DIM * H_DIM * K_DIM];

__device__ __forceinline__ uint32_t smem_u32(const void* p) {
    uint32_t a;
    asm("{ .reg .u64 t; cvta.to.shared.u64 t, %1; cvt.u32.u64 %0, t; }" : "=r"(a) : "l"(p));
    return a;
}

#define CP_ASYNC16(dst, src) \
    asm volatile("cp.async.cg.shared.global [%0], [%1], 16;" \
        :: "r"((uint32_t)(dst)), "l"(src) : "memory")
#define CP_COMMIT() asm volatile("cp.async.commit_group;" ::: "memory")
#define CP_WAIT(n)  asm volatile("cp.async.wait_group %0;" :: "n"(n) : "memory")

#define LDSM_X4(r0,r1,r2,r3,addr) \
    asm volatile("ldmatrix.sync.aligned.m8n8.x4.shared.b16 {%0,%1,%2,%3}, [%4];" \
        : "=r"(r0), "=r"(r1), "=r"(r2), "=r"(r3) : "r"(addr))

// fp16-accumulate variant: D/C are 2x .f16x2 regs.
// reg0 = {c0,c1} (row r, cols 2i,2i+1), reg1 = {c2,c3} (row r+8) --
// identical packing to the fp32 version's fp16 stash.
#define MMA16816_F16(d, a, b0, b1) \
    asm volatile("mma.sync.aligned.m16n8k16.row.col.f16.f16.f16.f16 " \
        "{%0,%1}, {%2,%3,%4,%5}, {%6,%7}, {%0,%1};" \
        : "+r"((d)[0]), "+r"((d)[1]) \
        : "r"((a)[0]), "r"((a)[1]), "r"((a)[2]), "r"((a)[3]), "r"(b0), "r"(b1))

// ---------------- merged prep kernel (known-good) ----------------
__global__ void prep_kernel(const float* __restrict__ W0, const float* __restrict__ w,
                            const int* __restrict__ ip,
                            const float* __restrict__ x, const float* __restrict__ logvar,
                            float* __restrict__ out, int out_size) {
    size_t t = (size_t)blockIdx.x * blockDim.x + threadIdx.x;
    size_t e = t * 4;
    int j = (int)(e >> 18);          // H*K = 2^18
    int k = (int)(e & (K_DIM - 1));
    float4 a = *reinterpret_cast<const float4*>(W0 + e);
    const float* wip = w + (size_t)ip[0] * J_DIM * K_DIM + (size_t)j * K_DIM + k;
    float4 b = *reinterpret_cast<const float4*>(wip);
    __half2 h0 = __floats2half2_rn(a.x * b.x * SCALE_F, a.y * b.y * SCALE_F);
    __half2 h1 = __floats2half2_rn(a.z * b.z * SCALE_F, a.w * b.w * SCALE_F);
    uint2 pk;
    pk.x = *reinterpret_cast<uint32_t*>(&h0);
    pk.y = *reinterpret_cast<uint32_t*>(&h1);
    *reinterpret_cast<uint2*>(g_w0h + e) = pk;

    if (t < (B_DIM * K_DIM) / 4) {
        float4 v = reinterpret_cast<const float4*>(x)[t];
        __half2 x0 = __floats2half2_rn(v.x, v.y);
        __half2 x1 = __floats2half2_rn(v.z, v.w);
        uint2 xp;
        xp.x = *reinterpret_cast<uint32_t*>(&x0);
        xp.y = *reinterpret_cast<uint32_t*>(&x1);
        reinterpret_cast<uint2*>(g_xh)[t] = xp;
    }
    if (blockIdx.x == 0) {
        int extra = out_size - B_DIM * J_DIM;
        if ((int)threadIdx.x < extra && threadIdx.x < D_DIM)
            out[B_DIM * J_DIM + threadIdx.x] = logvar[threadIdx.x];
    }
}

// ---------------- fused grouped-GEMM + overlapped epilogue (fp16 acc) ----------------
// Identical structure to the 435.6us best (R6); only the accumulator dtype changes.
__global__ void __launch_bounds__(256, 1)
encoder_gemm(const float* __restrict__ b0g, const float* __restrict__ W1g,
             const float* __restrict__ b1g, float* __restrict__ out) {
    extern __shared__ char smem[];
    const uint32_t S_X = smem_u32(smem);            // 131072 B
    const uint32_t S_W = S_X + 131072;              // 2 x 32768 B
    float2* bw   = reinterpret_cast<float2*>(smem + 196608);  // 512 float2
    float*  sums = reinterpret_cast<float*>(smem + 200704);   // 128 floats

    const int tid  = threadIdx.x;
    const int wid  = tid >> 5;
    const int lane = tid & 31;
    const int wm = wid & 1;          // M block (64 rows)
    const int wn = wid >> 1;         // N block (32 cols within 128 h-chunk)
    const int j  = blockIdx.x >> 3;
    const int mt8 = blockIdx.x & 7;

    const __half* Ab = g_xh + (size_t)(mt8 * 128) * K_DIM;
    const __half* Bb = g_w0h + (size_t)j * H_DIM * K_DIM;

    for (int c = tid; c < H_DIM; c += 256)
        bw[c] = make_float2(b0g[j * H_DIM + c], W1g[j * H_DIM + c]);
    if (tid < 128) sums[tid] = 0.f;

    // X tile: 8192 16B chunks, xor-swizzled (64 chunks per 1024B row)
#pragma unroll
    for (int it = 0; it < 32; ++it) {
        int c = tid + it * 256;
        int row = c >> 6, kb = c & 63;
        int swz = (kb & 56) | ((kb ^ row) & 7);
        CP_ASYNC16(S_X + row * 1024 + swz * 16, Ab + (size_t)row * K_DIM + kb * 8);
    }

    // W chunk stage: cc in [0,16): hc = cc>>2, kc = cc&3. 128h x 128k, 256B/row.
    auto stage_w = [&](int cc, int buf) {
        const __half* src = Bb + (size_t)((cc >> 2) * 128) * K_DIM + (cc & 3) * 128;
        uint32_t dstb = S_W + buf * 32768;
#pragma unroll
        for (int it = 0; it < 8; ++it) {
            int c = tid + it * 256;
            int row = c >> 4, kb = c & 15;
            int swz = (kb & 8) | ((kb ^ row) & 7);
            CP_ASYNC16(dstb + row * 256 + swz * 16,
                       src + (size_t)row * K_DIM + kb * 8);
        }
    };

    stage_w(0, 0);
    CP_COMMIT();

    uint32_t acc[4][4][2];   // fp16x2 accumulators
#pragma unroll
    for (int mt = 0; mt < 4; ++mt)
#pragma unroll
        for (int nt = 0; nt < 4; ++nt) { acc[mt][nt][0] = 0u; acc[mt][nt][1] = 0u; }

    uint32_t stash[4][4][2];   // prev h-chunk acc (same packing)
    float mu[4][2];            // per-mt partial output dots
#pragma unroll
    for (int mt = 0; mt < 4; ++mt) { mu[mt][0] = 0.f; mu[mt][1] = 0.f; }

    const int a_row = wm * 64 + (lane & 15);
    const int a_ck  = lane >> 4;
    const int b_row = wn * 32 + (lane & 7) + ((lane >> 4) << 3);
    const int b_kb  = (lane >> 3) & 1;
    const int h_off = wn * 32 + (lane & 3) * 2;

    uint32_t afr[2][4][4], bfr[2][2][4];

    auto fetchA = [&](int kcL, int kk, uint32_t (&af)[4][4]) {
#pragma unroll
        for (int mt = 0; mt < 4; ++mt) {
            int r = a_row + mt * 16;
            int cidx = kcL * 16 + kk * 2 + a_ck;
            int swz = (cidx & 56) | ((cidx ^ r) & 7);
            LDSM_X4(af[mt][0], af[mt][1], af[mt][2], af[mt][3],
                    S_X + r * 1024 + swz * 16);
        }
    };
    auto fetchB = [&](uint32_t wbase, int kk, uint32_t (&bf)[2][4]) {
#pragma unroll
        for (int np = 0; np < 2; ++np) {
            int hl = b_row + np * 16;
            int kb = kk * 2 + b_kb;
            int swz = (kb & 8) | ((kb ^ hl) & 7);
            LDSM_X4(bf[np][0], bf[np][1], bf[np][2], bf[np][3],
                    wbase + hl * 256 + swz * 16);
        }
    };
    // one mt-slice of the deferred epilogue (reads fp16 stash, updates mu)
    auto epi_slice = [&](int mt, int hbase) {
        float sA = mu[mt][0], sB = mu[mt][1];
#pragma unroll
        for (int nt = 0; nt < 4; ++nt) {
            int h = hbase + h_off + nt * 8;
            float2 bw0 = bw[h];
            float2 bw1 = bw[h + 1];
            __half2 hp0 = *reinterpret_cast<__half2*>(&stash[mt][nt][0]);
            __half2 hp1 = *reinterpret_cast<__half2*>(&stash[mt][nt][1]);
            float2 p0 = __half22float2(hp0);
            float2 p1 = __half22float2(hp1);
            float v;
            v = fmaf(p0.x, INV_SCALE, bw0.x); v = (v > 0.f) ? v : 0.01f * v; sA = fmaf(v, bw0.y, sA);
            v = fmaf(p0.y, INV_SCALE, bw1.x); v = (v > 0.f) ? v : 0.01f * v; sA = fmaf(v, bw1.y, sA);
            v = fmaf(p1.x, INV_SCALE, bw0.x); v = (v > 0.f) ? v : 0.01f * v; sB = fmaf(v, bw0.y, sB);
            v = fmaf(p1.y, INV_SCALE, bw1.x); v = (v > 0.f) ? v : 0.01f * v; sB = fmaf(v, bw1.y, sB);
        }
        mu[mt][0] = sA; mu[mt][1] = sB;
    };

#pragma unroll 1
    for (int cc = 0; cc < 16; ++cc) {
        int buf = cc & 1;
        CP_WAIT(0);
        __syncthreads();

        uint32_t wbase = S_W + buf * 32768;
        int kc = cc & 3;
        const bool do_epi = (kc == 0) && (cc > 0);
        const int hbase = ((cc >> 2) - 1) * 128;   // only used when do_epi

        if (cc == 0) fetchA(0, 0, afr[0]);   // cold start; otherwise prefetched
        fetchB(wbase, 0, bfr[0]);
        if (cc < 15) { stage_w(cc + 1, buf ^ 1); CP_COMMIT(); }

#pragma unroll
        for (int kk = 0; kk < 8; ++kk) {
            int cur = kk & 1;
            if (kk < 7) {
                fetchA(kc, kk + 1, afr[cur ^ 1]);
                fetchB(wbase, kk + 1, bfr[cur ^ 1]);
            } else if (cc < 15) {
                // cross-barrier A prefetch (X tile is immutable)
                fetchA((cc + 1) & 3, 0, afr[0]);
            }
#pragma unroll
            for (int mt = 0; mt < 4; ++mt)
#pragma unroll
                for (int nt = 0; nt < 4; ++nt)
                    MMA16816_F16(acc[mt][nt], afr[cur][mt],
                                 bfr[cur][nt >> 1][(nt & 1) * 2],
                                 bfr[cur][nt >> 1][(nt & 1) * 2 + 1]);
            if (do_epi && (kk & 1)) epi_slice(kk >> 1, hbase);
        }

        if (kc == 3) {
            // stash finished h-chunk (already fp16-packed), clear acc
#pragma unroll
            for (int mt = 0; mt < 4; ++mt)
#pragma unroll
                for (int nt = 0; nt < 4; ++nt) {
                    stash[mt][nt][0] = acc[mt][nt][0];
                    stash[mt][nt][1] = acc[mt][nt][1];
                    acc[mt][nt][0] = 0u;
                    acc[mt][nt][1] = 0u;
                }
        }
    }

    // epilogue for last h-chunk (hc=3) + final reduction
#pragma unroll
    for (int mt = 0; mt < 4; ++mt) {
        epi_slice(mt, 3 * 128);
        float sA = mu[mt][0], sB = mu[mt][1];
        sA += __shfl_xor_sync(0xffffffffu, sA, 1);
        sA += __shfl_xor_sync(0xffffffffu, sA, 2);
        sB += __shfl_xor_sync(0xffffffffu, sB, 1);
        sB += __shfl_xor_sync(0xffffffffu, sB, 2);
        if ((lane & 3) == 0) {
            int row = wm * 64 + mt * 16 + (lane >> 2);
            atomicAdd(&sums[row], sA);
            atomicAdd(&sums[row + 8], sB);
        }
    }

    __syncthreads();
    if (tid < 128)
        out[(size_t)(mt8 * 128 + tid) * J_DIM + j] = sums[tid] + b1g[j];
}

// ---------------- launch ----------------
extern "C" void kernel_launch(void* const* d_in, const int* in_sizes, int n_in,
                              void* d_out, int out_size) {
    const float* x      = (const float*)d_in[0];
    const int*   ip     = (const int*)d_in[1];
    const float* w      = (const float*)d_in[2];
    const float* W0     = (const float*)d_in[3];
    const float* b0     = (const float*)d_in[4];
    const float* W1     = (const float*)d_in[5];
    const float* b1     = (const float*)d_in[6];
    const float* logvar = (const float*)d_in[7];
    float* out = (float*)d_out;

    const int SMEM_BYTES = 201216;
    cudaFuncSetAttribute(encoder_gemm, cudaFuncAttributeMaxDynamicSharedMemorySize, SMEM_BYTES);

    prep_kernel<<<(J_DIM * H_DIM * K_DIM / 4) / 256, 256>>>(W0, w, ip, x, logvar, out, out_size);
    encoder_gemm<<<J_DIM * (B_DIM / 128), 256, SMEM_BYTES>>>(b0, W1, b1, out);
}